// round 16
// baseline (speedup 1.0000x reference)
#include <cuda_runtime.h>
#include <stdint.h>

// x [n,c,h,w] fp32; per (n,c) row of hw=4096 keep top-k by |x|.
// out = x (kept) or x*(1-tau) (dropped).
// Persistent CTAs (256 thr), cp.async double-buffered row prefetch (R13
// structure). Slimmed smem (37 KB) for 6 resident CTAs/SM.
// Select per row (key = bits<<1): 10-bit histogram (1024 bins) -> scan ->
// crossing gather (+fused 8-bit hist) -> warp0: 256-bin scan, compact,
// 14-bit ballot search. Exact cold fallback + exact stable-tie path.

constexpr int HW      = 4096;
constexpr int THREADS = 256;
constexpr int EPT     = 16;
constexpr int NBIN    = 1024;            // 10-bit primary histogram
constexpr int CAP1    = 160;
constexpr int CAP2    = 64;
constexpr int GRID    = 888;             // 148 SMs x 6 resident CTAs
constexpr unsigned FULL = 0xFFFFFFFFu;

__device__ __forceinline__ void cp16(uint32_t saddr, const void* gptr) {
    asm volatile("cp.async.cg.shared.global [%0], [%1], 16;"
                 :: "r"(saddr), "l"(gptr));
}
__device__ __forceinline__ void cp_commit() {
    asm volatile("cp.async.commit_group;");
}
template <int N>
__device__ __forceinline__ void cp_wait() {
    asm volatile("cp.async.wait_group %0;" :: "n"(N));
}

__global__ __launch_bounds__(THREADS, 6)
void topk_blend_kernel(const float* __restrict__ x,
                       const float* __restrict__ tau_p,
                       const int*   __restrict__ k_p,
                       float*       __restrict__ out,
                       int rows)
{
    __shared__ uint32_t buf[2][HW];      // 32 KB row double-buffer
    __shared__ uint32_t hist[NBIN];      // 4 KB
    __shared__ uint32_t wtot[8];
    __shared__ uint32_t wtie[8];
    __shared__ uint32_t list1[CAP1];
    __shared__ uint32_t list2[CAP2];
    __shared__ uint32_t s_bin, s_krem, s_n1, s_T, s_need, s_mode, s_cnt;

    const int tid  = threadIdx.x;
    const int wid  = tid >> 5;
    const int lane = tid & 31;

    const float tau = __ldg(tau_p);
    const int   K   = __ldg(k_p);
    const float omt = 1.0f - tau;
    const bool  sel = (K > 0 && K < HW);
    const uint32_t Ku = (uint32_t)K;

    // zero hist once; phases keep it zeroed across iterations
    reinterpret_cast<uint4*>(hist)[tid] = make_uint4(0,0,0,0);
    __syncthreads();

    int row = blockIdx.x;
    if (row >= rows) return;

    uint32_t sbase[2];
    {
        uint32_t a;
        asm("{ .reg .u64 t; cvta.to.shared.u64 t, %1; cvt.u32.u64 %0, t; }"
            : "=r"(a) : "l"(&buf[0][0]));
        sbase[0] = a;
        sbase[1] = a + HW * 4;
    }

    // prologue: prefetch first row (thread t owns 16B chunks t+256j)
    {
        const float* g = x + (size_t)row * HW;
        #pragma unroll
        for (int j = 0; j < 4; j++)
            cp16(sbase[0] + (uint32_t)(tid + 256*j) * 16, g + (tid + 256*j) * 4);
        cp_commit();
    }
    int cur = 0;

    while (true) {
        const int  nrow      = row + GRID;
        const bool have_next = (nrow < rows);

        if (have_next) {
            const float* g = x + (size_t)nrow * HW;
            #pragma unroll
            for (int j = 0; j < 4; j++)
                cp16(sbase[cur^1] + (uint32_t)(tid + 256*j) * 16, g + (tid + 256*j) * 4);
            cp_commit();
            cp_wait<1>();        // current row's group complete
        } else {
            cp_wait<0>();
        }

        // ---- own chunks smem -> regs (conflict-free LDS.128) ----
        uint32_t b[EPT];
        {
            const uint4* bu = reinterpret_cast<const uint4*>(&buf[cur][0]);
            #pragma unroll
            for (int j = 0; j < 4; j++) {
                uint4 v = bu[tid + 256*j];
                b[j*4+0] = v.x; b[j*4+1] = v.y; b[j*4+2] = v.z; b[j*4+3] = v.w;
            }
        }

        // ================= SELECT =================
        uint32_t T = 0, need = 0;
        bool geq = false;

        if (sel) {
            // ----- 10-bit histogram (key bits 31..22) -----
            #pragma unroll
            for (int j = 0; j < EPT; j++)
                atomicAdd(&hist[(b[j] >> 21) & 0x3FFu], 1u);
            __syncthreads();                                    // S1

            // ----- scan 1024 bins (4/thread), self-zeroing -----
            {
                uint4 h = reinterpret_cast<uint4*>(hist)[tid];
                reinterpret_cast<uint4*>(hist)[tid] = make_uint4(0,0,0,0);
                uint32_t c[4] = {h.x, h.y, h.z, h.w};
                uint32_t suf[4];
                suf[3] = c[3];
                suf[2] = c[2] + suf[3];
                suf[1] = c[1] + suf[2];
                suf[0] = c[0] + suf[1];
                const uint32_t tot = suf[0];

                uint32_t s = tot;
                #pragma unroll
                for (int off = 1; off < 32; off <<= 1) {
                    uint32_t v = __shfl_down_sync(FULL, s, off);
                    if (lane + off < 32) s += v;
                }
                const uint32_t lane_hi = s - tot;
                if (lane == 0) wtot[wid] = s;
                __syncthreads();                                // S2

                uint32_t warp_hi = 0;
                #pragma unroll
                for (int w = 0; w < 8; w++) if (w > wid) warp_hi += wtot[w];
                const uint32_t off = lane_hi + warp_hi;
                #pragma unroll
                for (int i = 0; i < 4; i++) {
                    uint32_t incl  = suf[i] + off;
                    uint32_t above = incl - c[i];
                    if (above < Ku && Ku <= incl) {
                        s_bin  = (uint32_t)(tid * 4 + i);
                        s_krem = Ku - above;
                    }
                }
                if (tid == 0) s_n1 = 0;
            }
            __syncthreads();                                    // S3

            const uint32_t binsel = s_bin;
            const uint32_t krem1  = s_krem;

            // ----- crossing gather + fused 8-bit hist (bits 21..14) -----
            #pragma unroll
            for (int j = 0; j < EPT; j++) {
                uint32_t key = b[j] << 1;
                if ((key >> 22) == binsel) {
                    uint32_t rem = key & 0x3FFFFFu;
                    uint32_t pos = atomicAdd(&s_n1, 1u);
                    if (pos < CAP1) list1[pos] = rem;
                    atomicAdd(&hist[rem >> 14], 1u);
                }
            }
            __syncthreads();                                    // S4
            const uint32_t n1 = s_n1;

            // ----- warp0: 256-bin scan + compact + 14-bit ballot search ----
            if (wid == 0) {
                uint4 h0 = reinterpret_cast<uint4*>(hist)[lane*2+0];
                uint4 h1 = reinterpret_cast<uint4*>(hist)[lane*2+1];
                reinterpret_cast<uint4*>(hist)[lane*2+0] = make_uint4(0,0,0,0);
                reinterpret_cast<uint4*>(hist)[lane*2+1] = make_uint4(0,0,0,0);

                if (n1 <= CAP1) {
                    uint32_t c[8] = {h0.x,h0.y,h0.z,h0.w,h1.x,h1.y,h1.z,h1.w};
                    uint32_t suf[8];
                    suf[7] = c[7];
                    #pragma unroll
                    for (int i = 6; i >= 0; i--) suf[i] = c[i] + suf[i+1];
                    const uint32_t tot = suf[0];
                    uint32_t s = tot;
                    #pragma unroll
                    for (int off = 1; off < 32; off <<= 1) {
                        uint32_t v = __shfl_down_sync(FULL, s, off);
                        if (lane + off < 32) s += v;
                    }
                    const uint32_t lane_hi = s - tot;

                    uint32_t bin2 = 0, krem2 = 0;
                    bool found = false;
                    #pragma unroll
                    for (int i = 0; i < 8; i++) {
                        uint32_t incl  = suf[i] + lane_hi;
                        uint32_t above = incl - c[i];
                        if (above < krem1 && krem1 <= incl) {
                            found = true;
                            bin2  = (uint32_t)(lane * 8 + i);
                            krem2 = krem1 - above;
                        }
                    }
                    unsigned fm = __ballot_sync(FULL, found);
                    int src = __ffs(fm) - 1;
                    bin2  = __shfl_sync(FULL, bin2,  src);
                    krem2 = __shfl_sync(FULL, krem2, src);

                    // compact subclass (ballot prefix)
                    uint32_t nout = 0;
                    #pragma unroll
                    for (int i = 0; i < CAP1/32; i++) {
                        int idx = lane + 32 * i;
                        uint32_t v = (idx < (int)n1) ? list1[idx] : 0u;
                        bool mq = (idx < (int)n1) && ((v >> 14) == bin2);
                        unsigned mm = __ballot_sync(FULL, mq);
                        if (mq) {
                            int pos = (int)nout + __popc(mm & ((1u << lane) - 1u));
                            if (pos < CAP2) list2[pos] = v & 0x3FFFu;
                        }
                        nout += (uint32_t)__popc(mm);
                    }

                    if (nout <= CAP2) {
                        uint32_t cand[2]; bool val[2];
                        #pragma unroll
                        for (int i = 0; i < 2; i++) {
                            int idx = lane + 32 * i;
                            val[i]  = idx < (int)nout;
                            cand[i] = val[i] ? list2[idx] : 0u;
                        }
                        auto cnt_ge = [&](uint32_t t) -> uint32_t {
                            uint32_t n = 0;
                            #pragma unroll
                            for (int i = 0; i < 2; i++)
                                n += (uint32_t)__popc(__ballot_sync(FULL, val[i] && cand[i] >= t));
                            return n;
                        };
                        uint32_t v = 0;
                        #pragma unroll
                        for (int bit = 13; bit >= 0; bit--) {
                            uint32_t t = v | (1u << bit);
                            if (cnt_ge(t) >= krem2) v = t;
                        }
                        uint32_t n_gt = cnt_ge(v + 1);
                        uint32_t n_eq = cnt_ge(v) - n_gt;
                        uint32_t nd   = krem2 - n_gt;
                        if (lane == 0) {
                            s_T    = (binsel << 22) | (bin2 << 14) | v;
                            s_need = nd;
                            s_mode = (nd == n_eq) ? 1u : 0u;
                        }
                    } else if (lane == 0) {
                        s_mode = 2u;
                    }
                } else if (lane == 0) {
                    s_mode = 2u;
                }
            }
            __syncthreads();                                    // S5

            const uint32_t mode = s_mode;
            if (mode != 2u) {
                T    = s_T;
                need = s_need;
                geq  = (mode == 1u);
            } else {
                // ----- exact cold fallback: counting binary search -----
                uint32_t Tf = 0;
                for (int bit = 30; bit >= 0; bit--) {
                    if (tid == 0) s_cnt = 0;
                    __syncthreads();
                    uint32_t trial = Tf | (1u << bit);
                    uint32_t cnt = 0;
                    #pragma unroll
                    for (int j = 0; j < EPT; j++) cnt += ((b[j] << 1) >= trial);
                    #pragma unroll
                    for (int off = 16; off >= 1; off >>= 1)
                        cnt += __shfl_down_sync(FULL, cnt, off);
                    if (lane == 0) atomicAdd(&s_cnt, cnt);
                    __syncthreads();
                    if (s_cnt >= Ku) Tf = trial;
                    __syncthreads();
                }
                uint32_t n_ge = 0, n_gt = 0;
                {
                    if (tid == 0) s_cnt = 0;
                    __syncthreads();
                    uint32_t cnt = 0;
                    #pragma unroll
                    for (int j = 0; j < EPT; j++) cnt += ((b[j] << 1) >= Tf);
                    #pragma unroll
                    for (int off = 16; off >= 1; off >>= 1)
                        cnt += __shfl_down_sync(FULL, cnt, off);
                    if (lane == 0) atomicAdd(&s_cnt, cnt);
                    __syncthreads();
                    n_ge = s_cnt;
                    __syncthreads();
                    if (tid == 0) s_cnt = 0;
                    __syncthreads();
                    cnt = 0;
                    #pragma unroll
                    for (int j = 0; j < EPT; j++) cnt += ((b[j] << 1) > Tf);
                    #pragma unroll
                    for (int off = 16; off >= 1; off >>= 1)
                        cnt += __shfl_down_sync(FULL, cnt, off);
                    if (lane == 0) atomicAdd(&s_cnt, cnt);
                    __syncthreads();
                    n_gt = s_cnt;
                }
                T    = Tf;
                need = Ku - n_gt;
                geq  = (need == (n_ge - n_gt));
            }
        }

        // ================= APPLY =================
        if (!sel || geq) {
            const bool keepall = (K >= HW);
            float4* __restrict__ yout =
                reinterpret_cast<float4*>(out + (size_t)row * HW);
            #pragma unroll
            for (int j = 0; j < 4; j++) {
                float r[4];
                #pragma unroll
                for (int q = 0; q < 4; q++) {
                    const int idx = j * 4 + q;
                    float xv = __uint_as_float(b[idx]);
                    bool keep = sel ? ((b[idx] << 1) >= T) : keepall;
                    r[q] = keep ? xv : xv * omt;
                }
                yout[tid + 256*j] = make_float4(r[0], r[1], r[2], r[3]);
            }
        } else {
            // rare tie path: exact stable ranks in index order from SMEM
            const uint32_t* bu = &buf[cur][0];
            int myeq = 0;
            #pragma unroll
            for (int j = 0; j < EPT; j++)
                myeq += ((bu[tid*16 + j] << 1) == T);
            uint32_t e = (uint32_t)myeq;
            #pragma unroll
            for (int off = 1; off < 32; off <<= 1) {
                uint32_t v = __shfl_up_sync(FULL, e, off);
                if (lane >= off) e += v;
            }
            if (lane == 31) wtie[wid] = e;
            __syncthreads();
            uint32_t lo = 0;
            #pragma unroll
            for (int w = 0; w < 8; w++) if (w < wid) lo += wtie[w];
            int rank = (int)(e - (uint32_t)myeq + lo);

            const int needi = (int)need;
            float4* __restrict__ yout =
                reinterpret_cast<float4*>(out + (size_t)row * HW);
            #pragma unroll
            for (int i = 0; i < 4; i++) {
                float r[4];
                #pragma unroll
                for (int q = 0; q < 4; q++) {
                    uint32_t bits = bu[tid*16 + i*4 + q];
                    uint32_t key  = bits << 1;
                    bool keep = (key > T) | ((key == T) & (rank < needi));
                    rank += (key == T);
                    float xv = __uint_as_float(bits);
                    r[q] = keep ? xv : xv * omt;
                }
                yout[tid*4 + i] = make_float4(r[0], r[1], r[2], r[3]);
            }
            __syncthreads();   // protect buf[cur] from next iteration's prefetch
        }

        if (!have_next) break;
        cur ^= 1;
        row = nrow;
    }
}

extern "C" void kernel_launch(void* const* d_in, const int* in_sizes, int n_in,
                              void* d_out, int out_size)
{
    const float* x   = (const float*)d_in[0];
    const float* tau = (const float*)d_in[1];
    const int*   k   = (const int*)d_in[2];
    float*       out = (float*)d_out;
    const int    rows = in_sizes[0] / HW;   // n*c = 8192

    const int grid = (rows < GRID) ? rows : GRID;
    topk_blend_kernel<<<grid, THREADS>>>(x, tau, k, out, rows);
}

// round 17
// speedup vs baseline: 3.7852x; 3.7852x over previous
#include <cuda_runtime.h>
#include <stdint.h>

// x [n,c,h,w] fp32; per (n,c) row of hw=4096 keep top-k by |x|.
// out = x (kept) or x*(1-tau) (dropped).
// R13 select structure (proven 83.4us) + DYNAMIC row scheduling via a global
// counter to remove the 11-vs-12-row tail imbalance of static striding.
// Persistent CTAs (256 thr), cp.async double-buffered row prefetch; the next
// row index is fetched by thread 0 at loop top and published by the existing
// S1 barrier; its prefetch issues right after S1.
// Select per row (key = bits<<1): 11-bit histogram (2048 bins) -> scan ->
// crossing gather (+fused 8-bit hist) -> warp0: 256-bin scan, compact,
// 13-bit ballot search. Exact cold fallback + exact stable-tie path.

constexpr int HW      = 4096;
constexpr int THREADS = 256;
constexpr int EPT     = 16;
constexpr int NBIN    = 2048;
constexpr int BPT     = NBIN / THREADS;  // 8
constexpr int CAP1    = 256;
constexpr int CAP2    = 64;
constexpr int GRID    = 740;             // 148 SMs x 5 resident CTAs
constexpr unsigned FULL = 0xFFFFFFFFu;

__device__ int g_ctr;                    // next row to hand out

__global__ void reset_ctr(int start) { g_ctr = start; }

__device__ __forceinline__ void cp16(uint32_t saddr, const void* gptr) {
    asm volatile("cp.async.cg.shared.global [%0], [%1], 16;"
                 :: "r"(saddr), "l"(gptr));
}
__device__ __forceinline__ void cp_commit() {
    asm volatile("cp.async.commit_group;");
}
template <int N>
__device__ __forceinline__ void cp_wait() {
    asm volatile("cp.async.wait_group %0;" :: "n"(N));
}

__global__ __launch_bounds__(THREADS, 5)
void topk_blend_kernel(const float* __restrict__ x,
                       const float* __restrict__ tau_p,
                       const int*   __restrict__ k_p,
                       float*       __restrict__ out,
                       int rows)
{
    __shared__ uint32_t buf[2][HW];      // 32 KB row double-buffer
    __shared__ uint32_t hist[NBIN];
    __shared__ uint32_t wtot[8];
    __shared__ uint32_t wtie[8];
    __shared__ uint32_t list1[CAP1];
    __shared__ uint32_t list2[CAP2];
    __shared__ uint32_t s_bin, s_krem, s_n1, s_T, s_need, s_mode, s_cnt;
    __shared__ int      s_nrow;

    const int tid  = threadIdx.x;
    const int wid  = tid >> 5;
    const int lane = tid & 31;

    const float tau = __ldg(tau_p);
    const int   K   = __ldg(k_p);
    const float omt = 1.0f - tau;
    const bool  sel = (K > 0 && K < HW);
    const uint32_t Ku = (uint32_t)K;

    // zero hist once; phases keep it zeroed across iterations
    reinterpret_cast<uint4*>(hist)[tid*2+0] = make_uint4(0,0,0,0);
    reinterpret_cast<uint4*>(hist)[tid*2+1] = make_uint4(0,0,0,0);
    __syncthreads();

    int row = blockIdx.x;
    if (row >= rows) return;

    uint32_t sbase[2];
    {
        uint32_t a;
        asm("{ .reg .u64 t; cvta.to.shared.u64 t, %1; cvt.u32.u64 %0, t; }"
            : "=r"(a) : "l"(&buf[0][0]));
        sbase[0] = a;
        sbase[1] = a + HW * 4;
    }

    // prologue: prefetch first row (thread t owns 16B chunks t+256j)
    {
        const float* g = x + (size_t)row * HW;
        #pragma unroll
        for (int j = 0; j < 4; j++)
            cp16(sbase[0] + (uint32_t)(tid + 256*j) * 16, g + (tid + 256*j) * 4);
        cp_commit();
    }
    int cur = 0;

    while (true) {
        // grab next row index (published by the next barrier)
        if (tid == 0) s_nrow = atomicAdd(&g_ctr, 1);

        // own chunks of buf[cur] are ready once this thread's groups drain
        cp_wait<0>();
        uint32_t b[EPT];
        {
            const uint4* bu = reinterpret_cast<const uint4*>(&buf[cur][0]);
            #pragma unroll
            for (int j = 0; j < 4; j++) {
                uint4 v = bu[tid + 256*j];
                b[j*4+0] = v.x; b[j*4+1] = v.y; b[j*4+2] = v.z; b[j*4+3] = v.w;
            }
        }

        // ================= SELECT =================
        uint32_t T = 0, need = 0;
        bool geq = false;
        int  nrow;

        if (sel) {
            // ----- 11-bit histogram (key bits 31..21) -----
            #pragma unroll
            for (int j = 0; j < EPT; j++)
                atomicAdd(&hist[(b[j] >> 20) & 0x7FFu], 1u);
            __syncthreads();                                    // S1

            // next-row prefetch (index now visible to all threads)
            nrow = s_nrow;
            if (nrow < rows) {
                const float* g = x + (size_t)nrow * HW;
                #pragma unroll
                for (int j = 0; j < 4; j++)
                    cp16(sbase[cur^1] + (uint32_t)(tid + 256*j) * 16,
                         g + (tid + 256*j) * 4);
                cp_commit();
            }

            // ----- scan 2048 bins (8/thread), self-zeroing -----
            {
                uint4 h0 = reinterpret_cast<uint4*>(hist)[tid*2+0];
                uint4 h1 = reinterpret_cast<uint4*>(hist)[tid*2+1];
                reinterpret_cast<uint4*>(hist)[tid*2+0] = make_uint4(0,0,0,0);
                reinterpret_cast<uint4*>(hist)[tid*2+1] = make_uint4(0,0,0,0);
                uint32_t c[8] = {h0.x,h0.y,h0.z,h0.w,h1.x,h1.y,h1.z,h1.w};
                uint32_t suf[8];
                suf[7] = c[7];
                #pragma unroll
                for (int i = 6; i >= 0; i--) suf[i] = c[i] + suf[i+1];
                const uint32_t tot = suf[0];

                uint32_t s = tot;
                #pragma unroll
                for (int off = 1; off < 32; off <<= 1) {
                    uint32_t v = __shfl_down_sync(FULL, s, off);
                    if (lane + off < 32) s += v;
                }
                const uint32_t lane_hi = s - tot;
                if (lane == 0) wtot[wid] = s;
                __syncthreads();                                // S2

                uint32_t warp_hi = 0;
                #pragma unroll
                for (int w = 0; w < 8; w++) if (w > wid) warp_hi += wtot[w];
                const uint32_t off = lane_hi + warp_hi;
                #pragma unroll
                for (int i = 0; i < 8; i++) {
                    uint32_t incl  = suf[i] + off;
                    uint32_t above = incl - c[i];
                    if (above < Ku && Ku <= incl) {
                        s_bin  = (uint32_t)(tid * BPT + i);
                        s_krem = Ku - above;
                    }
                }
                if (tid == 0) s_n1 = 0;
            }
            __syncthreads();                                    // S3

            const uint32_t binsel = s_bin;
            const uint32_t krem1  = s_krem;

            // ----- crossing gather + fused 8-bit hist (bits 20..13) -----
            #pragma unroll
            for (int j = 0; j < EPT; j++) {
                uint32_t key = b[j] << 1;
                if ((key >> 21) == binsel) {
                    uint32_t rem = key & 0x1FFFFFu;
                    uint32_t pos = atomicAdd(&s_n1, 1u);
                    if (pos < CAP1) list1[pos] = rem;
                    atomicAdd(&hist[rem >> 13], 1u);
                }
            }
            __syncthreads();                                    // S4
            const uint32_t n1 = s_n1;

            // ----- warp0: 256-bin scan + compact + 13-bit ballot search ----
            if (wid == 0) {
                uint4 h0 = reinterpret_cast<uint4*>(hist)[lane*2+0];
                uint4 h1 = reinterpret_cast<uint4*>(hist)[lane*2+1];
                reinterpret_cast<uint4*>(hist)[lane*2+0] = make_uint4(0,0,0,0);
                reinterpret_cast<uint4*>(hist)[lane*2+1] = make_uint4(0,0,0,0);

                if (n1 <= CAP1) {
                    uint32_t c[8] = {h0.x,h0.y,h0.z,h0.w,h1.x,h1.y,h1.z,h1.w};
                    uint32_t suf[8];
                    suf[7] = c[7];
                    #pragma unroll
                    for (int i = 6; i >= 0; i--) suf[i] = c[i] + suf[i+1];
                    const uint32_t tot = suf[0];
                    uint32_t s = tot;
                    #pragma unroll
                    for (int off = 1; off < 32; off <<= 1) {
                        uint32_t v = __shfl_down_sync(FULL, s, off);
                        if (lane + off < 32) s += v;
                    }
                    const uint32_t lane_hi = s - tot;

                    uint32_t bin2 = 0, krem2 = 0;
                    bool found = false;
                    #pragma unroll
                    for (int i = 0; i < 8; i++) {
                        uint32_t incl  = suf[i] + lane_hi;
                        uint32_t above = incl - c[i];
                        if (above < krem1 && krem1 <= incl) {
                            found = true;
                            bin2  = (uint32_t)(lane * 8 + i);
                            krem2 = krem1 - above;
                        }
                    }
                    unsigned fm = __ballot_sync(FULL, found);
                    int src = __ffs(fm) - 1;
                    bin2  = __shfl_sync(FULL, bin2,  src);
                    krem2 = __shfl_sync(FULL, krem2, src);

                    // compact subclass (ballot prefix)
                    uint32_t nout = 0;
                    #pragma unroll
                    for (int i = 0; i < CAP1/32; i++) {
                        int idx = lane + 32 * i;
                        uint32_t v = (idx < (int)n1) ? list1[idx] : 0u;
                        bool mq = (idx < (int)n1) && ((v >> 13) == bin2);
                        unsigned mm = __ballot_sync(FULL, mq);
                        if (mq) {
                            int pos = (int)nout + __popc(mm & ((1u << lane) - 1u));
                            if (pos < CAP2) list2[pos] = v & 0x1FFFu;
                        }
                        nout += (uint32_t)__popc(mm);
                    }

                    if (nout <= CAP2) {
                        uint32_t cand[2]; bool val[2];
                        #pragma unroll
                        for (int i = 0; i < 2; i++) {
                            int idx = lane + 32 * i;
                            val[i]  = idx < (int)nout;
                            cand[i] = val[i] ? list2[idx] : 0u;
                        }
                        auto cnt_ge = [&](uint32_t t) -> uint32_t {
                            uint32_t n = 0;
                            #pragma unroll
                            for (int i = 0; i < 2; i++)
                                n += (uint32_t)__popc(__ballot_sync(FULL, val[i] && cand[i] >= t));
                            return n;
                        };
                        uint32_t v = 0;
                        #pragma unroll
                        for (int bit = 12; bit >= 0; bit--) {
                            uint32_t t = v | (1u << bit);
                            if (cnt_ge(t) >= krem2) v = t;
                        }
                        uint32_t n_gt = cnt_ge(v + 1);
                        uint32_t n_eq = cnt_ge(v) - n_gt;
                        uint32_t nd   = krem2 - n_gt;
                        if (lane == 0) {
                            s_T    = (binsel << 21) | (bin2 << 13) | v;
                            s_need = nd;
                            s_mode = (nd == n_eq) ? 1u : 0u;
                        }
                    } else if (lane == 0) {
                        s_mode = 2u;
                    }
                } else if (lane == 0) {
                    s_mode = 2u;
                }
            }
            __syncthreads();                                    // S5

            const uint32_t mode = s_mode;
            if (mode != 2u) {
                T    = s_T;
                need = s_need;
                geq  = (mode == 1u);
            } else {
                // ----- exact cold fallback: counting binary search -----
                uint32_t Tf = 0;
                for (int bit = 30; bit >= 0; bit--) {
                    if (tid == 0) s_cnt = 0;
                    __syncthreads();
                    uint32_t trial = Tf | (1u << bit);
                    uint32_t cnt = 0;
                    #pragma unroll
                    for (int j = 0; j < EPT; j++) cnt += ((b[j] << 1) >= trial);
                    #pragma unroll
                    for (int off = 16; off >= 1; off >>= 1)
                        cnt += __shfl_down_sync(FULL, cnt, off);
                    if (lane == 0) atomicAdd(&s_cnt, cnt);
                    __syncthreads();
                    if (s_cnt >= Ku) Tf = trial;
                    __syncthreads();
                }
                uint32_t n_ge = 0, n_gt = 0;
                {
                    if (tid == 0) s_cnt = 0;
                    __syncthreads();
                    uint32_t cnt = 0;
                    #pragma unroll
                    for (int j = 0; j < EPT; j++) cnt += ((b[j] << 1) >= Tf);
                    #pragma unroll
                    for (int off = 16; off >= 1; off >>= 1)
                        cnt += __shfl_down_sync(FULL, cnt, off);
                    if (lane == 0) atomicAdd(&s_cnt, cnt);
                    __syncthreads();
                    n_ge = s_cnt;
                    __syncthreads();
                    if (tid == 0) s_cnt = 0;
                    __syncthreads();
                    cnt = 0;
                    #pragma unroll
                    for (int j = 0; j < EPT; j++) cnt += ((b[j] << 1) > Tf);
                    #pragma unroll
                    for (int off = 16; off >= 1; off >>= 1)
                        cnt += __shfl_down_sync(FULL, cnt, off);
                    if (lane == 0) atomicAdd(&s_cnt, cnt);
                    __syncthreads();
                    n_gt = s_cnt;
                }
                T    = Tf;
                need = Ku - n_gt;
                geq  = (need == (n_ge - n_gt));
            }
        } else {
            // cold: K degenerate — publish nrow, prefetch, keep barrier pairing
            __syncthreads();
            nrow = s_nrow;
            if (nrow < rows) {
                const float* g = x + (size_t)nrow * HW;
                #pragma unroll
                for (int j = 0; j < 4; j++)
                    cp16(sbase[cur^1] + (uint32_t)(tid + 256*j) * 16,
                         g + (tid + 256*j) * 4);
                cp_commit();
            }
            __syncthreads();
        }

        // ================= APPLY =================
        if (!sel || geq) {
            const bool keepall = (K >= HW);
            float4* __restrict__ yout =
                reinterpret_cast<float4*>(out + (size_t)row * HW);
            #pragma unroll
            for (int j = 0; j < 4; j++) {
                float r[4];
                #pragma unroll
                for (int q = 0; q < 4; q++) {
                    const int idx = j * 4 + q;
                    float xv = __uint_as_float(b[idx]);
                    bool keep = sel ? ((b[idx] << 1) >= T) : keepall;
                    r[q] = keep ? xv : xv * omt;
                }
                yout[tid + 256*j] = make_float4(r[0], r[1], r[2], r[3]);
            }
        } else {
            // rare tie path: exact stable ranks in index order from SMEM
            const uint32_t* bu = &buf[cur][0];
            int myeq = 0;
            #pragma unroll
            for (int j = 0; j < EPT; j++)
                myeq += ((bu[tid*16 + j] << 1) == T);
            uint32_t e = (uint32_t)myeq;
            #pragma unroll
            for (int off = 1; off < 32; off <<= 1) {
                uint32_t v = __shfl_up_sync(FULL, e, off);
                if (lane >= off) e += v;
            }
            if (lane == 31) wtie[wid] = e;
            __syncthreads();
            uint32_t lo = 0;
            #pragma unroll
            for (int w = 0; w < 8; w++) if (w < wid) lo += wtie[w];
            int rank = (int)(e - (uint32_t)myeq + lo);

            const int needi = (int)need;
            float4* __restrict__ yout =
                reinterpret_cast<float4*>(out + (size_t)row * HW);
            #pragma unroll
            for (int i = 0; i < 4; i++) {
                float r[4];
                #pragma unroll
                for (int q = 0; q < 4; q++) {
                    uint32_t bits = bu[tid*16 + i*4 + q];
                    uint32_t key  = bits << 1;
                    bool keep = (key > T) | ((key == T) & (rank < needi));
                    rank += (key == T);
                    float xv = __uint_as_float(bits);
                    r[q] = keep ? xv : xv * omt;
                }
                yout[tid*4 + i] = make_float4(r[0], r[1], r[2], r[3]);
            }
            __syncthreads();   // tie reads of buf[cur] done before next S1
        }

        if (nrow >= rows) break;
        cur ^= 1;
        row = nrow;
    }
}

extern "C" void kernel_launch(void* const* d_in, const int* in_sizes, int n_in,
                              void* d_out, int out_size)
{
    const float* x   = (const float*)d_in[0];
    const float* tau = (const float*)d_in[1];
    const int*   k   = (const int*)d_in[2];
    float*       out = (float*)d_out;
    const int    rows = in_sizes[0] / HW;   // n*c = 8192

    const int grid = (rows < GRID) ? rows : GRID;
    reset_ctr<<<1, 1>>>(grid);
    topk_blend_kernel<<<grid, THREADS>>>(x, tau, k, out, rows);
}